// round 1
// baseline (speedup 1.0000x reference)
#include <cuda_runtime.h>
#include <cuda_bf16.h>
#include <cstdint>

#define N_R   100000
#define N_E   1200000
#define G_N   4096
#define H     64
#define ED    16
#define LYR   4

// ---------------- scratch (device globals; allocation-free) ----------------
__device__ float g_h[(size_t)N_R * H];
__device__ float g_agg[(size_t)N_R * H];
__device__ float g_hs[N_R];
__device__ float g_hd[N_R];
__device__ float g_ecsr[(size_t)N_E * H];     // edge embeddings in CSR (dst-sorted) order
__device__ float g_ea[LYR * N_E];             // per-layer edge logit term, CSR order
__device__ int   g_deg[N_R];
__device__ int   g_off[N_R + 1];
__device__ int   g_cur[N_R];
__device__ int   g_srcs[N_E];                 // src node per CSR slot
__device__ int   g_perm[N_E];                 // original edge id per CSR slot
__device__ int   g_gcnt[G_N];
__device__ int   g_goff[G_N + 1];
__device__ float g_w16[LYR * ED];             // W_e @ a_e[l]  (16-dim per layer)
__device__ float g_pooled[(size_t)G_N * H];

// ---------------- small utility kernels ----------------
__global__ void zero_int(int* p, int n) {
    int i = blockIdx.x * blockDim.x + threadIdx.x;
    if (i < n) p[i] = 0;
}

__global__ void copy_int(int* dst, const int* src, int n) {
    int i = blockIdx.x * blockDim.x + threadIdx.x;
    if (i < n) dst[i] = src[i];
}

__global__ void hist_kernel(const int* __restrict__ idx, int* __restrict__ cnt, int n) {
    int i = blockIdx.x * blockDim.x + threadIdx.x;
    if (i < n) atomicAdd(&cnt[idx[i]], 1);
}

// exclusive scan: off[0]=0, off[i+1]=sum(cnt[0..i]).  single block, 1024 threads.
__global__ void scan_excl(const int* __restrict__ cnt, int* __restrict__ off, int n) {
    __shared__ int warp_sums[32];
    __shared__ int s_base;
    int tid = threadIdx.x;
    if (tid == 0) { s_base = 0; off[0] = 0; }
    __syncthreads();
    for (int start = 0; start < n; start += 1024) {
        int i = start + tid;
        int v = (i < n) ? cnt[i] : 0;
        int x = v;
        #pragma unroll
        for (int d = 1; d < 32; d <<= 1) {
            int y = __shfl_up_sync(0xffffffffu, x, d);
            if ((tid & 31) >= d) x += y;
        }
        if ((tid & 31) == 31) warp_sums[tid >> 5] = x;
        __syncthreads();
        if (tid < 32) {
            int w = warp_sums[tid];
            #pragma unroll
            for (int d = 1; d < 32; d <<= 1) {
                int y = __shfl_up_sync(0xffffffffu, w, d);
                if (tid >= d) w += y;
            }
            warp_sums[tid] = w;
        }
        __syncthreads();
        int warp_prefix = (tid >= 32) ? warp_sums[(tid >> 5) - 1] : 0;
        int incl = s_base + warp_prefix + x;
        if (i < n) off[i + 1] = incl;
        __syncthreads();
        if (tid == 1023) s_base = incl;
        __syncthreads();
    }
}

__global__ void scatter_kernel(const int* __restrict__ src, const int* __restrict__ dst,
                               int* __restrict__ cur, int* __restrict__ perm,
                               int* __restrict__ srcs, int n) {
    int e = blockIdx.x * blockDim.x + threadIdx.x;
    if (e < n) {
        int d = dst[e];
        int p = atomicAdd(&cur[d], 1);
        perm[p] = e;
        srcs[p] = src[e];
    }
}

// w16[l][k] = sum_j W_e[k][j] * a_e[l][j]     (64 threads)
__global__ void w16_kernel(const float* __restrict__ W_e, const float* __restrict__ a_e,
                           float* __restrict__ w16) {
    int t = threadIdx.x;
    if (t < LYR * ED) {
        int l = t >> 4, k = t & 15;
        float s = 0.f;
        for (int j = 0; j < H; j++) s += W_e[k * H + j] * a_e[l * H + j];
        w16[t] = s;
    }
}

// ---------------- node matvec: out = maybe_lrelu(resid + in @ W), fused a_s/a_d dots
__global__ void matvec_kernel(const float* __restrict__ in, const float* __restrict__ W,
                              const float* __restrict__ resid, float* __restrict__ out,
                              const float* __restrict__ as_, const float* __restrict__ ad_,
                              float* __restrict__ hs, float* __restrict__ hd,
                              int n, int do_lrelu) {
    __shared__ float sW[64 * 64];
    __shared__ float sIn[64 * 64];
    for (int i = threadIdx.x; i < 4096; i += 256) sW[i] = W[i];
    int lane = threadIdx.x & 31;
    int w = threadIdx.x >> 5;
    float as0 = 0.f, as1 = 0.f, ad0 = 0.f, ad1 = 0.f;
    if (as_) { as0 = as_[2 * lane]; as1 = as_[2 * lane + 1];
               ad0 = ad_[2 * lane]; ad1 = ad_[2 * lane + 1]; }
    const float2* sW2 = (const float2*)sW;
    int ntiles = (n + 63) / 64;
    for (int t = blockIdx.x; t < ntiles; t += gridDim.x) {
        int base = t * 64;
        __syncthreads();
        for (int i = threadIdx.x; i < 4096; i += 256) {
            int node = base + (i >> 6);
            sIn[i] = (node < n) ? in[(size_t)node * H + (i & 63)] : 0.f;
        }
        __syncthreads();
        int r0 = w * 8;
        float acc[8][2];
        #pragma unroll
        for (int r = 0; r < 8; r++) { acc[r][0] = 0.f; acc[r][1] = 0.f; }
        for (int k = 0; k < 64; k++) {
            float2 wp = sW2[k * 32 + lane];
            #pragma unroll
            for (int r = 0; r < 8; r++) {
                float b = sIn[(r0 + r) * 64 + k];
                acc[r][0] += b * wp.x;
                acc[r][1] += b * wp.y;
            }
        }
        #pragma unroll
        for (int r = 0; r < 8; r++) {
            int node = base + r0 + r;
            if (node >= n) break;
            float v0 = acc[r][0], v1 = acc[r][1];
            if (resid) {
                float2 rr = *(const float2*)(resid + (size_t)node * H + 2 * lane);
                v0 += rr.x; v1 += rr.y;
            }
            if (do_lrelu) {
                v0 = v0 > 0.f ? v0 : 0.1f * v0;
                v1 = v1 > 0.f ? v1 : 0.1f * v1;
            }
            *(float2*)(out + (size_t)node * H + 2 * lane) = make_float2(v0, v1);
            if (as_) {
                float ps = v0 * as0 + v1 * as1;
                float pd = v0 * ad0 + v1 * ad1;
                #pragma unroll
                for (int d = 16; d; d >>= 1) {
                    ps += __shfl_xor_sync(0xffffffffu, ps, d);
                    pd += __shfl_xor_sync(0xffffffffu, pd, d);
                }
                if (lane == 0) { hs[node] = ps; hd[node] = pd; }
            }
        }
    }
}

// ---------------- build edge embeddings (CSR order) + per-layer logit terms
__global__ void build_e_kernel(const float* __restrict__ r_edge,
                               const float* __restrict__ W_e,
                               const int* __restrict__ perm,
                               const float* __restrict__ w16,
                               float* __restrict__ ecsr, float* __restrict__ ea,
                               int n_e) {
    __shared__ float sWe[ED * H];   // 4KB
    __shared__ float sw16[LYR * ED];
    for (int i = threadIdx.x; i < ED * H; i += 256) sWe[i] = W_e[i];
    if (threadIdx.x < LYR * ED) sw16[threadIdx.x] = w16[threadIdx.x];
    __syncthreads();
    int lane = threadIdx.x & 31;
    int warp = (blockIdx.x * blockDim.x + threadIdx.x) >> 5;
    int nwarps = (gridDim.x * blockDim.x) >> 5;
    const float2* sWe2 = (const float2*)sWe;
    for (int p = warp; p < n_e; p += nwarps) {
        int eid = perm[p];
        const float4* rp = (const float4*)(r_edge + (size_t)eid * ED);
        float4 q0 = rp[0], q1 = rp[1], q2 = rp[2], q3 = rp[3];
        float r[16] = {q0.x, q0.y, q0.z, q0.w, q1.x, q1.y, q1.z, q1.w,
                       q2.x, q2.y, q2.z, q2.w, q3.x, q3.y, q3.z, q3.w};
        float e0 = 0.f, e1 = 0.f;
        #pragma unroll
        for (int k = 0; k < 16; k++) {
            float2 wp = sWe2[k * 32 + lane];
            e0 += r[k] * wp.x;
            e1 += r[k] * wp.y;
        }
        *(float2*)(ecsr + (size_t)p * H + 2 * lane) = make_float2(e0, e1);
        if (lane < LYR) {
            float s = 0.f;
            #pragma unroll
            for (int k = 0; k < 16; k++) s += r[k] * sw16[lane * ED + k];
            ea[(size_t)lane * N_E + p] = s;
        }
    }
}

// ---------------- attention layer: warp per dst node, single-pass online softmax
__global__ void layer_kernel(const int* __restrict__ off, const int* __restrict__ srcs,
                             const float* __restrict__ ea, const float* __restrict__ hs,
                             const float* __restrict__ hd, const float* __restrict__ h,
                             const float* __restrict__ ecsr, float* __restrict__ agg, int n) {
    int wid = (blockIdx.x * blockDim.x + threadIdx.x) >> 5;
    int lane = threadIdx.x & 31;
    if (wid >= n) return;
    int beg = off[wid], end = off[wid + 1];
    float hdn = hd[wid];
    float m = -1e30f, s = 0.f, v0 = 0.f, v1 = 0.f;
    for (int p = beg; p < end; p++) {
        int sv = srcs[p];
        float logit = hs[sv] + hdn + ea[p];
        logit = logit > 0.f ? logit : 0.1f * logit;
        float mn = fmaxf(m, logit);
        float c = __expf(m - mn);
        float wv = __expf(logit - mn);
        float2 hp = *(const float2*)(h + (size_t)sv * H + 2 * lane);
        float2 ep = *(const float2*)(ecsr + (size_t)p * H + 2 * lane);
        s = s * c + wv;
        v0 = v0 * c + wv * (hp.x + ep.x);
        v1 = v1 * c + wv * (hp.y + ep.y);
        m = mn;
    }
    float inv = (end > beg) ? (1.0f / s) : 0.f;
    *(float2*)(agg + (size_t)wid * H + 2 * lane) = make_float2(v0 * inv, v1 * inv);
}

// ---------------- gate + interaction mixing + pooling (warp per graph)
__global__ void pool_kernel(const int* __restrict__ goff, const float* __restrict__ d_edge,
                            const float* __restrict__ w_d, const float* __restrict__ b_d,
                            const float* __restrict__ i_node, const float* __restrict__ W_i,
                            const float* __restrict__ h, float* __restrict__ pooled, int g_total) {
    int g = (blockIdx.x * blockDim.x + threadIdx.x) >> 5;
    int lane = threadIdx.x & 31;
    if (g >= g_total) return;
    float wd = w_d[0], bd = b_d[0];
    int beg = goff[g], end = goff[g + 1];
    float s00 = 0.f, s01 = 0.f, s10 = 0.f, s11 = 0.f, sg = 0.f;
    for (int nn = beg; nn < end; nn++) {
        float gate = 1.0f / (1.0f + __expf(-(d_edge[nn] * wd + bd)));
        float2 hp = *(const float2*)(h + (size_t)nn * H + 2 * lane);
        s00 += hp.x; s01 += hp.y;
        s10 += gate * hp.x; s11 += gate * hp.y;
        sg += gate;
    }
    float wi0 = W_i[2 * lane], wi1 = W_i[2 * lane + 1];
    float iv = i_node[g];
    float hi0 = iv * wi0 + s10;
    float hi1 = iv * wi1 + s11;
    float p0 = s00 + sg * hi0;
    float p1 = s01 + sg * hi1;
    *(float2*)(pooled + (size_t)g * H + 2 * lane) = make_float2(p0, p1);
}

// ---------------- MLP readout: 3x (relu(x@W+b)) then x@W_out+b_out
__global__ void mlp_kernel(const float* __restrict__ pooled, const float* __restrict__ W_mlp,
                           const float* __restrict__ b_mlp, const float* __restrict__ W_out,
                           const float* __restrict__ b_out, float* __restrict__ out, int g_total) {
    __shared__ float sW[4096];
    __shared__ float sx[4][64];
    __shared__ float sb[64];
    __shared__ float sWo[64];
    __shared__ float red[8];
    int tid = threadIdx.x;
    int local = tid >> 6, j = tid & 63;
    if (tid < 64) sWo[tid] = W_out[tid];
    int ngroups = (g_total + 3) / 4;
    for (int grp = blockIdx.x; grp < ngroups; grp += gridDim.x) {
        int g = grp * 4 + local;
        __syncthreads();
        sx[local][j] = (g < g_total) ? pooled[(size_t)g * H + j] : 0.f;
        for (int i = 0; i < 3; i++) {
            __syncthreads();
            for (int t = tid; t < 4096; t += 256) sW[t] = W_mlp[i * 4096 + t];
            if (tid < 64) sb[tid] = b_mlp[i * 64 + tid];
            __syncthreads();
            float acc = sb[j];
            for (int k = 0; k < 64; k++) acc += sx[local][k] * sW[k * 64 + j];
            acc = fmaxf(acc, 0.f);
            __syncthreads();
            sx[local][j] = acc;
        }
        __syncthreads();
        float part = sx[local][j] * sWo[j];
        #pragma unroll
        for (int d = 16; d; d >>= 1) part += __shfl_xor_sync(0xffffffffu, part, d);
        if ((tid & 31) == 0) red[tid >> 5] = part;
        __syncthreads();
        if (j == 0 && g < g_total) out[g] = red[2 * local] + red[2 * local + 1] + b_out[0];
    }
}

// ---------------- launcher ----------------
extern "C" void kernel_launch(void* const* d_in, const int* in_sizes, int n_in,
                              void* d_out, int out_size) {
    const float* r_node  = (const float*)d_in[0];
    const float* i_node  = (const float*)d_in[1];
    const float* r_edge  = (const float*)d_in[2];
    const float* d_edge  = (const float*)d_in[3];
    const int*   r2r_src = (const int*)d_in[4];
    const int*   r2r_dst = (const int*)d_in[5];
    const int*   graph_id= (const int*)d_in[6];
    const float* W_r     = (const float*)d_in[7];
    const float* W_i     = (const float*)d_in[8];
    const float* W_e     = (const float*)d_in[9];
    const float* Wm      = (const float*)d_in[10];
    const float* a_s     = (const float*)d_in[11];
    const float* a_d     = (const float*)d_in[12];
    const float* a_e     = (const float*)d_in[13];
    const float* w_d     = (const float*)d_in[14];
    const float* b_d     = (const float*)d_in[15];
    const float* W_mlp   = (const float*)d_in[16];
    const float* b_mlp   = (const float*)d_in[17];
    const float* W_out   = (const float*)d_in[18];
    const float* b_out   = (const float*)d_in[19];
    float* out = (float*)d_out;

    const int nN = in_sizes[3];        // N_R (d_edge is [N,1])
    const int nE = in_sizes[4];        // N_E
    const int nG = in_sizes[1];        // G (i_node is [G,1])

    // device-global scratch pointers
    float *p_h, *p_agg, *p_hs, *p_hd, *p_ecsr, *p_ea, *p_w16, *p_pooled;
    int *p_deg, *p_off, *p_cur, *p_srcs, *p_perm, *p_gcnt, *p_goff;
    cudaGetSymbolAddress((void**)&p_h, g_h);
    cudaGetSymbolAddress((void**)&p_agg, g_agg);
    cudaGetSymbolAddress((void**)&p_hs, g_hs);
    cudaGetSymbolAddress((void**)&p_hd, g_hd);
    cudaGetSymbolAddress((void**)&p_ecsr, g_ecsr);
    cudaGetSymbolAddress((void**)&p_ea, g_ea);
    cudaGetSymbolAddress((void**)&p_w16, g_w16);
    cudaGetSymbolAddress((void**)&p_pooled, g_pooled);
    cudaGetSymbolAddress((void**)&p_deg, g_deg);
    cudaGetSymbolAddress((void**)&p_off, g_off);
    cudaGetSymbolAddress((void**)&p_cur, g_cur);
    cudaGetSymbolAddress((void**)&p_srcs, g_srcs);
    cudaGetSymbolAddress((void**)&p_perm, g_perm);
    cudaGetSymbolAddress((void**)&p_gcnt, g_gcnt);
    cudaGetSymbolAddress((void**)&p_goff, g_goff);

    // --- CSR build (dst counting sort) + graph offsets ---
    zero_int<<<(nN + 255) / 256, 256>>>(p_deg, nN);
    zero_int<<<(nG + 255) / 256, 256>>>(p_gcnt, nG);
    hist_kernel<<<(nE + 255) / 256, 256>>>(r2r_dst, p_deg, nE);
    hist_kernel<<<(nN + 255) / 256, 256>>>(graph_id, p_gcnt, nN);
    scan_excl<<<1, 1024>>>(p_deg, p_off, nN);
    scan_excl<<<1, 1024>>>(p_gcnt, p_goff, nG);
    copy_int<<<(nN + 255) / 256, 256>>>(p_cur, p_off, nN);
    scatter_kernel<<<(nE + 255) / 256, 256>>>(r2r_src, r2r_dst, p_cur, p_perm, p_srcs, nE);

    // --- edge embeddings + per-layer logit terms ---
    w16_kernel<<<1, 64>>>(W_e, a_e, p_w16);
    build_e_kernel<<<1184, 256>>>(r_edge, W_e, p_perm, p_w16, p_ecsr, p_ea, nE);

    // --- node embedding h = r_node @ W_r, plus layer-0 attention dots ---
    matvec_kernel<<<592, 256>>>(r_node, W_r, nullptr, p_h, a_s, a_d, p_hs, p_hd, nN, 0);

    // --- 4 attention conv layers ---
    int layer_blocks = (nN + 7) / 8;   // one warp per dst node
    for (int l = 0; l < LYR; l++) {
        layer_kernel<<<layer_blocks, 256>>>(p_off, p_srcs, p_ea + (size_t)l * N_E,
                                            p_hs, p_hd, p_h, p_ecsr, p_agg, nN);
        const float* as_next = (l < LYR - 1) ? (a_s + (l + 1) * H) : nullptr;
        const float* ad_next = (l < LYR - 1) ? (a_d + (l + 1) * H) : nullptr;
        matvec_kernel<<<592, 256>>>(p_agg, Wm + (size_t)l * H * H, p_h, p_h,
                                    as_next, ad_next, p_hs, p_hd, nN, 1);
    }

    // --- gate / interaction mixing / pooling ---
    pool_kernel<<<(nG + 7) / 8, 256>>>(p_goff, d_edge, w_d, b_d, i_node, W_i,
                                       p_h, p_pooled, nG);

    // --- MLP readout ---
    mlp_kernel<<<64, 256>>>(p_pooled, W_mlp, b_mlp, W_out, b_out, out, nG);
}

// round 2
// speedup vs baseline: 1.2237x; 1.2237x over previous
#include <cuda_runtime.h>
#include <cuda_fp16.h>
#include <cstdint>

#define N_R   100000
#define N_E   1200000
#define G_N   4096
#define H     64
#define ED    16
#define LYR   4
#define CHUNK 128

// ---------------- scratch (device globals; allocation-free) ----------------
__device__ float   g_h[(size_t)N_R * H];
__device__ float   g_agg[(size_t)N_R * H];
__device__ float   g_hs[N_R];
__device__ float   g_hd[N_R];
__device__ __half2 g_ecsr[(size_t)N_E * (H / 2)];  // edge embeddings fp16, CSR order
__device__ float   g_ea[LYR * N_E];                // per-layer edge logit term, CSR order
__device__ int     g_deg[N_R];
__device__ int     g_off[N_R + 1];
__device__ int     g_cur[N_R];
__device__ int     g_srcs[N_E];
__device__ int     g_perm[N_E];
__device__ int     g_gcnt[G_N];
__device__ int     g_goff[G_N + 1];
__device__ float   g_w16[LYR * ED];
__device__ float   g_pooled[(size_t)G_N * H];
__device__ int     g_bsums[256];

// ---------------- small utility kernels ----------------
__global__ void zero_int(int* p, int n) {
    int i = blockIdx.x * blockDim.x + threadIdx.x;
    if (i < n) p[i] = 0;
}

__global__ void copy_int(int* dst, const int* src, int n) {
    int i = blockIdx.x * blockDim.x + threadIdx.x;
    if (i < n) dst[i] = src[i];
}

__global__ void hist_kernel(const int* __restrict__ idx, int* __restrict__ cnt, int n) {
    int i = blockIdx.x * blockDim.x + threadIdx.x;
    if (i < n) atomicAdd(&cnt[idx[i]], 1);
}

// ---- multi-block exclusive scan: off[0]=0, off[i+1]=inclusive(cnt[0..i]) ----
__global__ void scan_block(const int* __restrict__ cnt, int* __restrict__ off,
                           int* __restrict__ sums, int n) {
    __shared__ int wsum[32];
    int tid = threadIdx.x;
    int i = blockIdx.x * 1024 + tid;
    int v = (i < n) ? cnt[i] : 0;
    int x = v;
    #pragma unroll
    for (int d = 1; d < 32; d <<= 1) {
        int y = __shfl_up_sync(0xffffffffu, x, d);
        if ((tid & 31) >= d) x += y;
    }
    if ((tid & 31) == 31) wsum[tid >> 5] = x;
    __syncthreads();
    if (tid < 32) {
        int w = wsum[tid];
        #pragma unroll
        for (int d = 1; d < 32; d <<= 1) {
            int y = __shfl_up_sync(0xffffffffu, w, d);
            if (tid >= d) w += y;
        }
        wsum[tid] = w;
    }
    __syncthreads();
    int incl = x + ((tid >= 32) ? wsum[(tid >> 5) - 1] : 0);
    if (i < n) off[i + 1] = incl;
    if (tid == 1023) sums[blockIdx.x] = incl;
}

__global__ void scan_sums_serial(int* sums, int nb) {
    if (threadIdx.x == 0) {
        int acc = 0;
        for (int b = 0; b < nb; b++) { int t = sums[b]; sums[b] = acc; acc += t; }
    }
}

__global__ void add_base(int* __restrict__ off, const int* __restrict__ sums, int n) {
    int i = blockIdx.x * 1024 + threadIdx.x;
    if (i == 0) off[0] = 0;
    if (i < n) off[i + 1] += sums[blockIdx.x];
}

__global__ void scatter_kernel(const int* __restrict__ src, const int* __restrict__ dst,
                               int* __restrict__ cur, int* __restrict__ perm,
                               int* __restrict__ srcs, int n) {
    int e = blockIdx.x * blockDim.x + threadIdx.x;
    if (e < n) {
        int d = dst[e];
        int p = atomicAdd(&cur[d], 1);
        perm[p] = e;
        srcs[p] = src[e];
    }
}

// w16[l][k] = sum_j W_e[k][j] * a_e[l][j]
__global__ void w16_kernel(const float* __restrict__ W_e, const float* __restrict__ a_e,
                           float* __restrict__ w16) {
    int t = threadIdx.x;
    if (t < LYR * ED) {
        int l = t >> 4, k = t & 15;
        float s = 0.f;
        for (int j = 0; j < H; j++) s += W_e[k * H + j] * a_e[l * H + j];
        w16[t] = s;
    }
}

// ---------------- node matvec: out = maybe_lrelu(resid + in @ W), fused a_s/a_d dots
__global__ void matvec_kernel(const float* __restrict__ in, const float* __restrict__ W,
                              const float* __restrict__ resid, float* __restrict__ out,
                              const float* __restrict__ as_, const float* __restrict__ ad_,
                              float* __restrict__ hs, float* __restrict__ hd,
                              int n, int do_lrelu) {
    __shared__ float sW[64 * 64];
    __shared__ float sIn[64 * 64];
    for (int i = threadIdx.x; i < 4096; i += 256) sW[i] = W[i];
    int lane = threadIdx.x & 31;
    int w = threadIdx.x >> 5;
    float as0 = 0.f, as1 = 0.f, ad0 = 0.f, ad1 = 0.f;
    if (as_) { as0 = as_[2 * lane]; as1 = as_[2 * lane + 1];
               ad0 = ad_[2 * lane]; ad1 = ad_[2 * lane + 1]; }
    const float2* sW2 = (const float2*)sW;
    int ntiles = (n + 63) / 64;
    for (int t = blockIdx.x; t < ntiles; t += gridDim.x) {
        int base = t * 64;
        __syncthreads();
        for (int i = threadIdx.x; i < 4096; i += 256) {
            int node = base + (i >> 6);
            sIn[i] = (node < n) ? in[(size_t)node * H + (i & 63)] : 0.f;
        }
        __syncthreads();
        int r0 = w * 8;
        float acc[8][2];
        #pragma unroll
        for (int r = 0; r < 8; r++) { acc[r][0] = 0.f; acc[r][1] = 0.f; }
        for (int k = 0; k < 64; k++) {
            float2 wp = sW2[k * 32 + lane];
            #pragma unroll
            for (int r = 0; r < 8; r++) {
                float b = sIn[(r0 + r) * 64 + k];
                acc[r][0] += b * wp.x;
                acc[r][1] += b * wp.y;
            }
        }
        #pragma unroll
        for (int r = 0; r < 8; r++) {
            int node = base + r0 + r;
            if (node >= n) break;
            float v0 = acc[r][0], v1 = acc[r][1];
            if (resid) {
                float2 rr = *(const float2*)(resid + (size_t)node * H + 2 * lane);
                v0 += rr.x; v1 += rr.y;
            }
            if (do_lrelu) {
                v0 = v0 > 0.f ? v0 : 0.1f * v0;
                v1 = v1 > 0.f ? v1 : 0.1f * v1;
            }
            *(float2*)(out + (size_t)node * H + 2 * lane) = make_float2(v0, v1);
            if (as_) {
                float ps = v0 * as0 + v1 * as1;
                float pd = v0 * ad0 + v1 * ad1;
                #pragma unroll
                for (int d = 16; d; d >>= 1) {
                    ps += __shfl_xor_sync(0xffffffffu, ps, d);
                    pd += __shfl_xor_sync(0xffffffffu, pd, d);
                }
                if (lane == 0) { hs[node] = ps; hd[node] = pd; }
            }
        }
    }
}

// ---------------- build edge embeddings (fp16, CSR order) + per-layer logit terms
__global__ void build_e_kernel(const float* __restrict__ r_edge,
                               const float* __restrict__ W_e,
                               const int* __restrict__ perm,
                               const float* __restrict__ w16,
                               __half2* __restrict__ ecsr, float* __restrict__ ea,
                               int n_e) {
    __shared__ float sWe[ED * H];
    __shared__ float sw16[LYR * ED];
    for (int i = threadIdx.x; i < ED * H; i += 256) sWe[i] = W_e[i];
    if (threadIdx.x < LYR * ED) sw16[threadIdx.x] = w16[threadIdx.x];
    __syncthreads();
    int lane = threadIdx.x & 31;
    int warp = (blockIdx.x * blockDim.x + threadIdx.x) >> 5;
    int nwarps = (gridDim.x * blockDim.x) >> 5;
    const float2* sWe2 = (const float2*)sWe;
    for (int p = warp; p < n_e; p += nwarps) {
        int eid = __ldg(&perm[p]);
        const float4* rp = (const float4*)(r_edge + (size_t)eid * ED);
        float4 q0 = rp[0], q1 = rp[1], q2 = rp[2], q3 = rp[3];
        float r[16] = {q0.x, q0.y, q0.z, q0.w, q1.x, q1.y, q1.z, q1.w,
                       q2.x, q2.y, q2.z, q2.w, q3.x, q3.y, q3.z, q3.w};
        float e0 = 0.f, e1 = 0.f;
        #pragma unroll
        for (int k = 0; k < 16; k++) {
            float2 wp = sWe2[k * 32 + lane];
            e0 += r[k] * wp.x;
            e1 += r[k] * wp.y;
        }
        ecsr[(size_t)p * 32 + lane] = __floats2half2_rn(e0, e1);
        if (lane < LYR) {
            float s = 0.f;
            #pragma unroll
            for (int k = 0; k < 16; k++) s += r[k] * sw16[lane * ED + k];
            ea[(size_t)lane * N_E + p] = s;
        }
    }
}

// ---------------- attention layer: warp per dst node, warp-parallel softmax
// Phase A: lanes stride over edges -> logits to smem, warp-reduce max & sum.
// Phase B: independent weighted vector accumulation (pipelineable loads).
__global__ void layer_kernel(const int* __restrict__ off, const int* __restrict__ srcs,
                             const float* __restrict__ ea, const float* __restrict__ hs,
                             const float* __restrict__ hd, const float* __restrict__ h,
                             const __half2* __restrict__ ecsr, float* __restrict__ agg, int n) {
    __shared__ float s_w[8][CHUNK];
    __shared__ int   s_src[8][CHUNK];
    int wl = threadIdx.x >> 5;
    int lane = threadIdx.x & 31;
    int node = (blockIdx.x * blockDim.x + threadIdx.x) >> 5;
    if (node >= n) return;
    int beg = off[node], end = off[node + 1];
    float hdn = hd[node];
    float m_run = -1e30f, s_run = 0.f, v0 = 0.f, v1 = 0.f;
    for (int cs = beg; cs < end; cs += CHUNK) {
        int cnt = min(CHUNK, end - cs);
        // scalar phase: logits
        float mloc = -1e30f;
        for (int i = lane; i < cnt; i += 32) {
            int p = cs + i;
            int sv = __ldg(&srcs[p]);
            float lg = __ldg(&hs[sv]) + hdn + __ldg(&ea[p]);
            lg = lg > 0.f ? lg : 0.1f * lg;
            s_w[wl][i] = lg;
            s_src[wl][i] = sv;
            mloc = fmaxf(mloc, lg);
        }
        #pragma unroll
        for (int d = 16; d; d >>= 1) mloc = fmaxf(mloc, __shfl_xor_sync(0xffffffffu, mloc, d));
        float mn = fmaxf(m_run, mloc);
        __syncwarp();
        float sloc = 0.f;
        for (int i = lane; i < cnt; i += 32) {
            float wv = __expf(s_w[wl][i] - mn);
            s_w[wl][i] = wv;
            sloc += wv;
        }
        #pragma unroll
        for (int d = 16; d; d >>= 1) sloc += __shfl_xor_sync(0xffffffffu, sloc, d);
        float c = __expf(m_run - mn);
        s_run = s_run * c + sloc;
        v0 *= c; v1 *= c;
        __syncwarp();
        // vector phase: independent per-edge accumulation
        #pragma unroll 4
        for (int i = 0; i < cnt; i++) {
            float wv = s_w[wl][i];
            int sv = s_src[wl][i];
            float2 hp = *(const float2*)(h + (size_t)sv * H + 2 * lane);
            float2 ep = __half22float2(ecsr[(size_t)(cs + i) * 32 + lane]);
            v0 += wv * (hp.x + ep.x);
            v1 += wv * (hp.y + ep.y);
        }
        m_run = mn;
    }
    float inv = (end > beg) ? (1.0f / s_run) : 0.f;
    *(float2*)(agg + (size_t)node * H + 2 * lane) = make_float2(v0 * inv, v1 * inv);
}

// ---------------- gate + interaction mixing + pooling (warp per graph)
__global__ void pool_kernel(const int* __restrict__ goff, const float* __restrict__ d_edge,
                            const float* __restrict__ w_d, const float* __restrict__ b_d,
                            const float* __restrict__ i_node, const float* __restrict__ W_i,
                            const float* __restrict__ h, float* __restrict__ pooled, int g_total) {
    int g = (blockIdx.x * blockDim.x + threadIdx.x) >> 5;
    int lane = threadIdx.x & 31;
    if (g >= g_total) return;
    float wd = w_d[0], bd = b_d[0];
    int beg = goff[g], end = goff[g + 1];
    float s00 = 0.f, s01 = 0.f, s10 = 0.f, s11 = 0.f, sg = 0.f;
    for (int nn = beg; nn < end; nn++) {
        float gate = 1.0f / (1.0f + __expf(-(d_edge[nn] * wd + bd)));
        float2 hp = *(const float2*)(h + (size_t)nn * H + 2 * lane);
        s00 += hp.x; s01 += hp.y;
        s10 += gate * hp.x; s11 += gate * hp.y;
        sg += gate;
    }
    float wi0 = W_i[2 * lane], wi1 = W_i[2 * lane + 1];
    float iv = i_node[g];
    float hi0 = iv * wi0 + s10;
    float hi1 = iv * wi1 + s11;
    *(float2*)(pooled + (size_t)g * H + 2 * lane) =
        make_float2(s00 + sg * hi0, s01 + sg * hi1);
}

// ---------------- MLP readout: 3x (relu(x@W+b)) then x@W_out+b_out
__global__ void mlp_kernel(const float* __restrict__ pooled, const float* __restrict__ W_mlp,
                           const float* __restrict__ b_mlp, const float* __restrict__ W_out,
                           const float* __restrict__ b_out, float* __restrict__ out, int g_total) {
    __shared__ float sW[4096];
    __shared__ float sx[4][64];
    __shared__ float sb[64];
    __shared__ float sWo[64];
    __shared__ float red[8];
    int tid = threadIdx.x;
    int local = tid >> 6, j = tid & 63;
    if (tid < 64) sWo[tid] = W_out[tid];
    int ngroups = (g_total + 3) / 4;
    for (int grp = blockIdx.x; grp < ngroups; grp += gridDim.x) {
        int g = grp * 4 + local;
        __syncthreads();
        sx[local][j] = (g < g_total) ? pooled[(size_t)g * H + j] : 0.f;
        for (int i = 0; i < 3; i++) {
            __syncthreads();
            for (int t = tid; t < 4096; t += 256) sW[t] = W_mlp[i * 4096 + t];
            if (tid < 64) sb[tid] = b_mlp[i * 64 + tid];
            __syncthreads();
            float acc = sb[j];
            for (int k = 0; k < 64; k++) acc += sx[local][k] * sW[k * 64 + j];
            acc = fmaxf(acc, 0.f);
            __syncthreads();
            sx[local][j] = acc;
        }
        __syncthreads();
        float part = sx[local][j] * sWo[j];
        #pragma unroll
        for (int d = 16; d; d >>= 1) part += __shfl_xor_sync(0xffffffffu, part, d);
        if ((tid & 31) == 0) red[tid >> 5] = part;
        __syncthreads();
        if (j == 0 && g < g_total) out[g] = red[2 * local] + red[2 * local + 1] + b_out[0];
    }
}

// ---------------- launcher ----------------
extern "C" void kernel_launch(void* const* d_in, const int* in_sizes, int n_in,
                              void* d_out, int out_size) {
    const float* r_node  = (const float*)d_in[0];
    const float* i_node  = (const float*)d_in[1];
    const float* r_edge  = (const float*)d_in[2];
    const float* d_edge  = (const float*)d_in[3];
    const int*   r2r_src = (const int*)d_in[4];
    const int*   r2r_dst = (const int*)d_in[5];
    const int*   graph_id= (const int*)d_in[6];
    const float* W_r     = (const float*)d_in[7];
    const float* W_i     = (const float*)d_in[8];
    const float* W_e     = (const float*)d_in[9];
    const float* Wm      = (const float*)d_in[10];
    const float* a_s     = (const float*)d_in[11];
    const float* a_d     = (const float*)d_in[12];
    const float* a_e     = (const float*)d_in[13];
    const float* w_d     = (const float*)d_in[14];
    const float* b_d     = (const float*)d_in[15];
    const float* W_mlp   = (const float*)d_in[16];
    const float* b_mlp   = (const float*)d_in[17];
    const float* W_out   = (const float*)d_in[18];
    const float* b_out   = (const float*)d_in[19];
    float* out = (float*)d_out;

    const int nN = in_sizes[3];
    const int nE = in_sizes[4];
    const int nG = in_sizes[1];

    float *p_h, *p_agg, *p_hs, *p_hd, *p_ea, *p_w16, *p_pooled;
    __half2* p_ecsr;
    int *p_deg, *p_off, *p_cur, *p_srcs, *p_perm, *p_gcnt, *p_goff, *p_bsums;
    cudaGetSymbolAddress((void**)&p_h, g_h);
    cudaGetSymbolAddress((void**)&p_agg, g_agg);
    cudaGetSymbolAddress((void**)&p_hs, g_hs);
    cudaGetSymbolAddress((void**)&p_hd, g_hd);
    cudaGetSymbolAddress((void**)&p_ecsr, g_ecsr);
    cudaGetSymbolAddress((void**)&p_ea, g_ea);
    cudaGetSymbolAddress((void**)&p_w16, g_w16);
    cudaGetSymbolAddress((void**)&p_pooled, g_pooled);
    cudaGetSymbolAddress((void**)&p_deg, g_deg);
    cudaGetSymbolAddress((void**)&p_off, g_off);
    cudaGetSymbolAddress((void**)&p_cur, g_cur);
    cudaGetSymbolAddress((void**)&p_srcs, g_srcs);
    cudaGetSymbolAddress((void**)&p_perm, g_perm);
    cudaGetSymbolAddress((void**)&p_gcnt, g_gcnt);
    cudaGetSymbolAddress((void**)&p_goff, g_goff);
    cudaGetSymbolAddress((void**)&p_bsums, g_bsums);

    // --- CSR build (dst counting sort) + graph offsets ---
    zero_int<<<(nN + 255) / 256, 256>>>(p_deg, nN);
    zero_int<<<(nG + 255) / 256, 256>>>(p_gcnt, nG);
    hist_kernel<<<(nE + 255) / 256, 256>>>(r2r_dst, p_deg, nE);
    hist_kernel<<<(nN + 255) / 256, 256>>>(graph_id, p_gcnt, nN);

    int nbN = (nN + 1023) / 1024;
    scan_block<<<nbN, 1024>>>(p_deg, p_off, p_bsums, nN);
    scan_sums_serial<<<1, 32>>>(p_bsums, nbN);
    add_base<<<nbN, 1024>>>(p_off, p_bsums, nN);

    int nbG = (nG + 1023) / 1024;
    scan_block<<<nbG, 1024>>>(p_gcnt, p_goff, p_bsums, nG);
    scan_sums_serial<<<1, 32>>>(p_bsums, nbG);
    add_base<<<nbG, 1024>>>(p_goff, p_bsums, nG);

    copy_int<<<(nN + 255) / 256, 256>>>(p_cur, p_off, nN);
    scatter_kernel<<<(nE + 255) / 256, 256>>>(r2r_src, r2r_dst, p_cur, p_perm, p_srcs, nE);

    // --- edge embeddings + per-layer logit terms ---
    w16_kernel<<<1, 64>>>(W_e, a_e, p_w16);
    build_e_kernel<<<2048, 256>>>(r_edge, W_e, p_perm, p_w16, p_ecsr, p_ea, nE);

    // --- node embedding h = r_node @ W_r, plus layer-0 attention dots ---
    matvec_kernel<<<592, 256>>>(r_node, W_r, nullptr, p_h, a_s, a_d, p_hs, p_hd, nN, 0);

    // --- 4 attention conv layers ---
    int layer_blocks = (nN + 7) / 8;
    for (int l = 0; l < LYR; l++) {
        layer_kernel<<<layer_blocks, 256>>>(p_off, p_srcs, p_ea + (size_t)l * N_E,
                                            p_hs, p_hd, p_h, p_ecsr, p_agg, nN);
        const float* as_next = (l < LYR - 1) ? (a_s + (l + 1) * H) : nullptr;
        const float* ad_next = (l < LYR - 1) ? (a_d + (l + 1) * H) : nullptr;
        matvec_kernel<<<592, 256>>>(p_agg, Wm + (size_t)l * H * H, p_h, p_h,
                                    as_next, ad_next, p_hs, p_hd, nN, 1);
    }

    // --- gate / interaction mixing / pooling ---
    pool_kernel<<<(nG + 7) / 8, 256>>>(p_goff, d_edge, w_d, b_d, i_node, W_i,
                                       p_h, p_pooled, nG);

    // --- MLP readout ---
    mlp_kernel<<<64, 256>>>(p_pooled, W_mlp, b_mlp, W_out, b_out, out, nG);
}